// round 11
// baseline (speedup 1.0000x reference)
#include <cuda_runtime.h>
#include <cuda_bf16.h>
#include <math.h>

// ---------------- problem constants ----------------
#define BATCH 8
#define T 4096
#define BT (BATCH*T)          // 32768
#define DIM 768
#define EMB 768
#define MFEAT 384
#define NB 4
#define KQV_OUT 2304
#define PRM_SCALE 0.051031036307982884f   // 1/sqrt(384)
#define EPS 1e-8f

// ---------------- scratch (device globals; no cudaMalloc allowed) ----------
__device__ float g_o1  [(size_t)BT*768];        // monarch stage-1 output (permuted)
__device__ float g_kqv [(size_t)BT*KQV_OUT];    // k|q|v concatenated
__device__ float g_kp  [(size_t)BT*MFEAT];
__device__ float g_qp  [(size_t)BT*MFEAT];
__device__ float g_xdk [BT];
__device__ float g_xdq [BT];
__device__ float g_kpart[BATCH*32*MFEAT];
__device__ float g_ksum [BATCH*MFEAT];
__device__ float g_kptv [(size_t)BATCH*EMB*MFEAT];
__device__ float g_dinv [BT];
__device__ float g_y   [(size_t)BT*768];

// ---------------- generic NT SGEMM: C = A (MxK, row-major) * B^T (B is NxK row-major)
// tile 128x64x16, 256 threads, 8x4 per thread
#define GBM 128
#define GBN 64
#define GBK 16

// epilogue modes
#define MODE_NONE 0
#define MODE_EXP  1   // v = exp(acc - rowv[row]) * scale
#define MODE_RSC  2   // v = acc * rowv[row]

__global__ __launch_bounds__(256)
void gemm_nt(const float* __restrict__ A, int lda, long long aZoff,
             const float* __restrict__ Bm, long long bZoff, int K,
             float* __restrict__ C, int ldc, int cs, int czCo, long long cZoff,
             const float* __restrict__ bias,
             const float* __restrict__ rowv, int rvz,
             int mode, float scale)
{
    const int z = blockIdx.z;
    const float* Ab = A + (size_t)z * aZoff;
    const float* Bb = Bm + (size_t)z * bZoff;
    float*       Cb = C + (size_t)z * cZoff;

    const int rowBase = blockIdx.y * GBM;
    const int colBase = blockIdx.x * GBN;

    __shared__ __align__(16) float As[GBK][GBM + 4];  // stride 132 floats (528B, 16B-mult)
    __shared__ __align__(16) float Bs[GBK][GBN + 4];  // stride 68  floats (272B, 16B-mult)

    const int tid = threadIdx.x;
    const int tx = tid & 15;
    const int ty = tid >> 4;

    float acc[8][4];
#pragma unroll
    for (int i = 0; i < 8; i++)
#pragma unroll
        for (int j = 0; j < 4; j++) acc[i][j] = 0.f;

    const int nK = K / GBK;
    for (int kb = 0; kb < nK; ++kb) {
        const int k0 = kb * GBK;
        // A tile: 128 rows x 16 cols (2048 elems, 8/thread)
#pragma unroll
        for (int i = 0; i < 8; i++) {
            int idx = tid + i * 256;
            int r = idx >> 4, c = idx & 15;
            As[c][r] = Ab[(size_t)(rowBase + r) * lda + (k0 + c)];
        }
        // B tile: 64 rows x 16 cols (1024 elems, 4/thread); B is NxK row-major
#pragma unroll
        for (int i = 0; i < 4; i++) {
            int idx = tid + i * 256;
            int n = idx >> 4, c = idx & 15;
            Bs[c][n] = Bb[(size_t)(colBase + n) * K + (k0 + c)];
        }
        __syncthreads();
#pragma unroll
        for (int kk = 0; kk < GBK; ++kk) {
            float4 a0 = *reinterpret_cast<const float4*>(&As[kk][ty * 8]);
            float4 a1 = *reinterpret_cast<const float4*>(&As[kk][ty * 8 + 4]);
            float4 b0 = *reinterpret_cast<const float4*>(&Bs[kk][tx * 4]);
            float a[8] = {a0.x, a0.y, a0.z, a0.w, a1.x, a1.y, a1.z, a1.w};
            float b[4] = {b0.x, b0.y, b0.z, b0.w};
#pragma unroll
            for (int i = 0; i < 8; i++)
#pragma unroll
                for (int j = 0; j < 4; j++)
                    acc[i][j] = fmaf(a[i], b[j], acc[i][j]);
        }
        __syncthreads();
    }

    const int row0 = rowBase + ty * 8;
    const int colT = colBase + tx * 4;

    if (cs == 1) {
        // vectorized store path (prm_exp / y): no bias in these cases
#pragma unroll
        for (int i = 0; i < 8; i++) {
            float rv = 0.f;
            if (mode != MODE_NONE) rv = rowv[(size_t)z * rvz + row0 + i];
            float4 v;
            float t0 = acc[i][0], t1 = acc[i][1], t2 = acc[i][2], t3 = acc[i][3];
            if (mode == MODE_EXP) {
                v.x = expf(t0 - rv) * scale; v.y = expf(t1 - rv) * scale;
                v.z = expf(t2 - rv) * scale; v.w = expf(t3 - rv) * scale;
            } else if (mode == MODE_RSC) {
                v.x = t0 * rv; v.y = t1 * rv; v.z = t2 * rv; v.w = t3 * rv;
            } else {
                v.x = t0; v.y = t1; v.z = t2; v.w = t3;
            }
            *reinterpret_cast<float4*>(&Cb[(size_t)(row0 + i) * ldc + colT + z * czCo]) = v;
        }
    } else {
        // scattered store (monarch permutation): colMem = col*cs + z*czCo
#pragma unroll
        for (int i = 0; i < 8; i++) {
            size_t rbase = (size_t)(row0 + i) * ldc;
#pragma unroll
            for (int j = 0; j < 4; j++) {
                int cm = (colT + j) * cs + z * czCo;
                float v = acc[i][j];
                if (bias) v += bias[cm];
                Cb[rbase + cm] = v;
            }
        }
    }
}

// ---------------- TN SGEMM for kptv: C[n,m] = sum_t A[t,n] * B[t,m]
// A = v inside kqv (lda=2304, col offset baked into pointer), B = kp (ldb=384)
__global__ __launch_bounds__(256)
void gemm_tn_kptv(const float* __restrict__ A, int lda, long long aZoff,
                  const float* __restrict__ Bm, int ldb, long long bZoff,
                  float* __restrict__ C, int ldc, long long cZoff, int K)
{
    const int z = blockIdx.z;
    const float* Ab = A + (size_t)z * aZoff;
    const float* Bb = Bm + (size_t)z * bZoff;
    float*       Cb = C + (size_t)z * cZoff;

    const int nBase = blockIdx.y * GBM;   // M = 768 (n)
    const int mBase = blockIdx.x * GBN;   // N = 384 (m)

    __shared__ __align__(16) float As[GBK][GBM];  // stride 128 (512B)
    __shared__ __align__(16) float Bs[GBK][GBN];  // stride 64  (256B)

    const int tid = threadIdx.x;
    const int tx = tid & 15;
    const int ty = tid >> 4;

    float acc[8][4];
#pragma unroll
    for (int i = 0; i < 8; i++)
#pragma unroll
        for (int j = 0; j < 4; j++) acc[i][j] = 0.f;

    for (int k0 = 0; k0 < K; k0 += GBK) {
        // A tile: 16 t-rows x 128 n-cols
#pragma unroll
        for (int i = 0; i < 8; i++) {
            int idx = tid + i * 256;
            int r = idx & 127, c = idx >> 7;
            As[c][r] = Ab[(size_t)(k0 + c) * lda + nBase + r];
        }
        // B tile: 16 t-rows x 64 m-cols
#pragma unroll
        for (int i = 0; i < 4; i++) {
            int idx = tid + i * 256;
            int n = idx & 63, c = idx >> 6;
            Bs[c][n] = Bb[(size_t)(k0 + c) * ldb + mBase + n];
        }
        __syncthreads();
#pragma unroll
        for (int kk = 0; kk < GBK; ++kk) {
            float4 a0 = *reinterpret_cast<const float4*>(&As[kk][ty * 8]);
            float4 a1 = *reinterpret_cast<const float4*>(&As[kk][ty * 8 + 4]);
            float4 b0 = *reinterpret_cast<const float4*>(&Bs[kk][tx * 4]);
            float a[8] = {a0.x, a0.y, a0.z, a0.w, a1.x, a1.y, a1.z, a1.w};
            float b[4] = {b0.x, b0.y, b0.z, b0.w};
#pragma unroll
            for (int i = 0; i < 8; i++)
#pragma unroll
                for (int j = 0; j < 4; j++)
                    acc[i][j] = fmaf(a[i], b[j], acc[i][j]);
        }
        __syncthreads();
    }

    const int row0 = nBase + ty * 8;
    const int colT = mBase + tx * 4;
#pragma unroll
    for (int i = 0; i < 8; i++) {
        float4 v = make_float4(acc[i][0], acc[i][1], acc[i][2], acc[i][3]);
        *reinterpret_cast<float4*>(&Cb[(size_t)(row0 + i) * ldc + colT]) = v;
    }
}

// ---------------- helper kernels ----------------
// 0.5*||k||^2 and 0.5*||q||^2 per token (warp per (token,which))
__global__ void xd_kernel(const float* __restrict__ kqv,
                          float* __restrict__ xdk, float* __restrict__ xdq)
{
    int warp = (blockIdx.x * blockDim.x + threadIdx.x) >> 5;
    int lane = threadIdx.x & 31;
    int bt = warp >> 1;
    int which = warp & 1;
    if (bt >= BT) return;
    const float* v = kqv + (size_t)bt * KQV_OUT + which * 768;
    float s = 0.f;
#pragma unroll 6
    for (int e = lane; e < 768; e += 32) { float x = v[e]; s = fmaf(x, x, s); }
#pragma unroll
    for (int o = 16; o; o >>= 1) s += __shfl_xor_sync(0xffffffffu, s, o);
    if (lane == 0) { if (which) xdq[bt] = 0.5f * s; else xdk[bt] = 0.5f * s; }
}

// partial column sums of kp over t (deterministic two-stage)
__global__ void ksum_partial(const float* __restrict__ kp, float* __restrict__ kpart)
{
    int b = blockIdx.x >> 5;
    int chunk = blockIdx.x & 31;
    int m = threadIdx.x;                 // 384 threads
    const float* base = kp + ((size_t)b * T + (size_t)chunk * 128) * MFEAT + m;
    float s = 0.f;
#pragma unroll 8
    for (int t = 0; t < 128; t++) s += base[(size_t)t * MFEAT];
    kpart[((size_t)b * 32 + chunk) * MFEAT + m] = s;
}

__global__ void ksum_reduce(const float* __restrict__ kpart, float* __restrict__ ksum)
{
    int idx = blockIdx.x * blockDim.x + threadIdx.x;   // BATCH*MFEAT = 3072
    if (idx >= BATCH * MFEAT) return;
    int b = idx / MFEAT, m = idx % MFEAT;
    float s = 0.f;
#pragma unroll
    for (int c = 0; c < 32; c++) s += kpart[((size_t)b * 32 + c) * MFEAT + m];
    ksum[idx] = s;
}

// dinv[bt] = 1/(qp[bt,:].dot(ksum[b,:]) + eps)   (warp per token)
__global__ void dinv_kernel(const float* __restrict__ qp,
                            const float* __restrict__ ksum,
                            float* __restrict__ dinv)
{
    int warp = (blockIdx.x * blockDim.x + threadIdx.x) >> 5;
    int lane = threadIdx.x & 31;
    if (warp >= BT) return;
    int b = warp >> 12;                  // 4096 tokens per batch
    const float* q  = qp + (size_t)warp * MFEAT;
    const float* ks = ksum + (size_t)b * MFEAT;
    float s = 0.f;
#pragma unroll 3
    for (int m = lane; m < MFEAT; m += 32) s = fmaf(q[m], ks[m], s);
#pragma unroll
    for (int o = 16; o; o >>= 1) s += __shfl_xor_sync(0xffffffffu, s, o);
    if (lane == 0) dinv[warp] = 1.0f / (s + EPS);
}

// ---------------- launch ----------------
extern "C" void kernel_launch(void* const* d_in, const int* in_sizes, int n_in,
                              void* d_out, int out_size)
{
    const float* x       = (const float*)d_in[0];
    const float* kqv_w1  = (const float*)d_in[1];  // (4,192,192)
    const float* kqv_w2  = (const float*)d_in[2];  // (4,576,192)
    const float* kqv_b   = (const float*)d_in[3];  // (2304)
    const float* proj_w1 = (const float*)d_in[4];  // (4,192,192)
    const float* proj_w2 = (const float*)d_in[5];  // (4,192,192)
    const float* proj_b  = (const float*)d_in[6];  // (768)
    const float* w       = (const float*)d_in[7];  // (384,768)
    float* out = (float*)d_out;

    float *o1, *kqv, *kp, *qp, *xdk, *xdq, *kpart, *ksum, *kptv, *dinv, *y;
    cudaGetSymbolAddress((void**)&o1,   g_o1);
    cudaGetSymbolAddress((void**)&kqv,  g_kqv);
    cudaGetSymbolAddress((void**)&kp,   g_kp);
    cudaGetSymbolAddress((void**)&qp,   g_qp);
    cudaGetSymbolAddress((void**)&xdk,  g_xdk);
    cudaGetSymbolAddress((void**)&xdq,  g_xdq);
    cudaGetSymbolAddress((void**)&kpart,g_kpart);
    cudaGetSymbolAddress((void**)&ksum, g_ksum);
    cudaGetSymbolAddress((void**)&kptv, g_kptv);
    cudaGetSymbolAddress((void**)&dinv, g_dinv);
    cudaGetSymbolAddress((void**)&y,    g_y);

    // 1) kqv monarch stage 1: o1p[bt, q*4+kb] = sum_p x[bt, kb*192+p] * w1[kb,q,p]
    gemm_nt<<<dim3(192/GBN, BT/GBM, 4), 256>>>(
        x, DIM, 192, kqv_w1, 192*192, 192,
        o1, 768, /*cs*/4, /*czCo*/1, /*cZoff*/0,
        nullptr, nullptr, 0, MODE_NONE, 1.f);

    // 2) kqv monarch stage 2: kqv[bt, s*4+lb] = sum_r o1p[bt, lb*192+r]*w2[lb,s,r] + b
    gemm_nt<<<dim3(576/GBN, BT/GBM, 4), 256>>>(
        o1, 768, 192, kqv_w2, 576*192, 192,
        kqv, KQV_OUT, 4, 1, 0,
        kqv_b, nullptr, 0, MODE_NONE, 1.f);

    // 3) xd for k and q
    xd_kernel<<<(BT*2)/8, 256>>>(kqv, xdk, xdq);

    // 4) kp = exp(k@w^T - xdk)/sqrt(M)
    gemm_nt<<<dim3(MFEAT/GBN, BT/GBM, 1), 256>>>(
        kqv, KQV_OUT, 0, w, 0, 768,
        kp, MFEAT, 1, 0, 0,
        nullptr, xdk, 0, MODE_EXP, PRM_SCALE);

    // 5) qp = exp(q@w^T - xdq)/sqrt(M)
    gemm_nt<<<dim3(MFEAT/GBN, BT/GBM, 1), 256>>>(
        kqv + 768, KQV_OUT, 0, w, 0, 768,
        qp, MFEAT, 1, 0, 0,
        nullptr, xdq, 0, MODE_EXP, PRM_SCALE);

    // 6) ksum[b,m] = sum_t kp[b,t,m]
    ksum_partial<<<BATCH*32, MFEAT>>>(kp, kpart);
    ksum_reduce<<<(BATCH*MFEAT + 255)/256, 256>>>(kpart, ksum);

    // 7) kptv[b,n,m] = sum_t v[b,t,n]*kp[b,t,m]   (v = kqv cols 1536..2303)
    gemm_tn_kptv<<<dim3(MFEAT/GBN, EMB/GBM, BATCH), 256>>>(
        kqv + 1536, KQV_OUT, (long long)T * KQV_OUT,
        kp, MFEAT, (long long)T * MFEAT,
        kptv, MFEAT, (long long)EMB * MFEAT, T);

    // 8) dinv
    dinv_kernel<<<BT/8, 256>>>(qp, ksum, dinv);

    // 9) y[b,t,n] = (sum_m qp[b,t,m]*kptv[b,n,m]) * dinv[b,t]
    gemm_nt<<<dim3(EMB/GBN, T/GBM, BATCH), 256>>>(
        qp, MFEAT, (long long)T * MFEAT,
        kptv, (long long)EMB * MFEAT, MFEAT,
        y, EMB, 1, 0, (long long)T * EMB,
        nullptr, dinv, T, MODE_RSC, 1.f);

    // 10) proj monarch stage 1: o1p[bt, q*4+kb]
    gemm_nt<<<dim3(192/GBN, BT/GBM, 4), 256>>>(
        y, 768, 192, proj_w1, 192*192, 192,
        o1, 768, 4, 1, 0,
        nullptr, nullptr, 0, MODE_NONE, 1.f);

    // 11) proj monarch stage 2 -> output
    gemm_nt<<<dim3(192/GBN, BT/GBM, 4), 256>>>(
        o1, 768, 192, proj_w2, 192*192, 192,
        out, 768, 4, 1, 0,
        proj_b, nullptr, 0, MODE_NONE, 1.f);
}

// round 12
// speedup vs baseline: 1.2160x; 1.2160x over previous
#include <cuda_runtime.h>
#include <cuda_bf16.h>
#include <math.h>

// ---------------- problem constants ----------------
#define BATCH 8
#define T 4096
#define BT (BATCH*T)          // 32768
#define DIM 768
#define EMB 768
#define MFEAT 384
#define KQV_OUT 2304
#define PRM_SCALE 0.051031036307982884f   // 1/sqrt(384)
#define EPS 1e-8f

// ---------------- scratch (device globals) ----------------
__device__ float g_o1  [(size_t)BT*768];          // monarch stage-1 output (permuted)
__device__ float g_kqv [(size_t)BT*KQV_OUT];      // k|q|v concatenated
__device__ float g_kpq [(size_t)2*BT*MFEAT];      // kp then qp
__device__ float g_xd  [2*BT];                    // xdk then xdq
__device__ float g_kpart[BATCH*32*MFEAT];
__device__ float g_ksum [BATCH*MFEAT];
__device__ float g_kptvp[(size_t)BATCH*4*EMB*MFEAT]; // split-K partials
__device__ float g_kptv [(size_t)BATCH*EMB*MFEAT];
__device__ float g_dinv [BT];
__device__ float g_y   [(size_t)BT*768];

// ---------------- generic NT SGEMM: C = A (MxK, row-major) * B^T (B is NxK row-major)
// tile 256x64x16, 256 threads, 8x8 per thread (B cols split tx*4 and tx*4+32)
#define TM 256
#define TN 64
#define TK 16

#define MODE_NONE 0
#define MODE_EXP  1   // v = exp(acc - rowv[row]) * scale
#define MODE_RSC  2   // v = acc * rowv[row]

__global__ __launch_bounds__(256, 2)
void gemm_nt(const float* __restrict__ A, int lda, long long aZoff,
             const float* __restrict__ Bm, long long bZoff, int K,
             float* __restrict__ C, int ldc, int cs, int czCo, long long cZoff,
             const float* __restrict__ bias,
             const float* __restrict__ rowv, int rvz,
             int mode, float scale)
{
    const int z = blockIdx.z;
    const float* Ab = A + (size_t)z * aZoff;
    const float* Bb = Bm + (size_t)z * bZoff;
    float*       Cb = C + (size_t)z * cZoff;

    const int rowBase = blockIdx.y * TM;
    const int colBase = blockIdx.x * TN;

    __shared__ __align__(16) float As[TK][TM + 4];   // row stride 260 floats (16B mult)
    __shared__ __align__(16) float Bs[TK][TN + 4];   // row stride 68 floats

    const int tid = threadIdx.x;
    const int tx = tid & 7;        // n-group: cols tx*4.. and tx*4+32..
    const int ty = tid >> 3;       // m-group: rows ty*8..ty*8+7

    // staging register indices
    const int ar = (tid) >> 2;          // base A row for i=0
    const int ac4 = tid & 3;            // A f4-col
    const int br = tid >> 2;            // B row (0..63)
    const int bc4 = tid & 3;

    float4 stA[4];
    float4 stB;

    float acc[8][8];
#pragma unroll
    for (int i = 0; i < 8; i++)
#pragma unroll
        for (int j = 0; j < 8; j++) acc[i][j] = 0.f;

    const int nK = K / TK;

    // prologue loads (k0 = 0)
#pragma unroll
    for (int i = 0; i < 4; i++) {
        int r = ar + i * 64;
        stA[i] = *reinterpret_cast<const float4*>(&Ab[(size_t)(rowBase + r) * lda + ac4 * 4]);
    }
    stB = *reinterpret_cast<const float4*>(&Bb[(size_t)(colBase + br) * K + bc4 * 4]);

    int k0 = 0;
    for (int kb = 0; kb < nK; ++kb) {
        // store staged tile to smem (transposed to [k][m]/[k][n])
#pragma unroll
        for (int i = 0; i < 4; i++) {
            int r = ar + i * 64;
            As[ac4 * 4 + 0][r] = stA[i].x;
            As[ac4 * 4 + 1][r] = stA[i].y;
            As[ac4 * 4 + 2][r] = stA[i].z;
            As[ac4 * 4 + 3][r] = stA[i].w;
        }
        Bs[bc4 * 4 + 0][br] = stB.x;
        Bs[bc4 * 4 + 1][br] = stB.y;
        Bs[bc4 * 4 + 2][br] = stB.z;
        Bs[bc4 * 4 + 3][br] = stB.w;
        __syncthreads();

        if (kb + 1 < nK) {
            k0 += TK;
#pragma unroll
            for (int i = 0; i < 4; i++) {
                int r = ar + i * 64;
                stA[i] = *reinterpret_cast<const float4*>(&Ab[(size_t)(rowBase + r) * lda + k0 + ac4 * 4]);
            }
            stB = *reinterpret_cast<const float4*>(&Bb[(size_t)(colBase + br) * K + k0 + bc4 * 4]);
        }

#pragma unroll
        for (int kk = 0; kk < TK; ++kk) {
            float4 a0 = *reinterpret_cast<const float4*>(&As[kk][ty * 8]);
            float4 a1 = *reinterpret_cast<const float4*>(&As[kk][ty * 8 + 4]);
            float4 b0 = *reinterpret_cast<const float4*>(&Bs[kk][tx * 4]);
            float4 b1 = *reinterpret_cast<const float4*>(&Bs[kk][tx * 4 + 32]);
            float a[8] = {a0.x, a0.y, a0.z, a0.w, a1.x, a1.y, a1.z, a1.w};
            float b[8] = {b0.x, b0.y, b0.z, b0.w, b1.x, b1.y, b1.z, b1.w};
#pragma unroll
            for (int i = 0; i < 8; i++)
#pragma unroll
                for (int j = 0; j < 8; j++)
                    acc[i][j] = fmaf(a[i], b[j], acc[i][j]);
        }
        __syncthreads();
    }

    const int row0 = rowBase + ty * 8;
    const int c0 = colBase + tx * 4;        // acc[][0..3]
    const int c1 = c0 + 32;                 // acc[][4..7]

    if (cs == 1) {
#pragma unroll
        for (int i = 0; i < 8; i++) {
            float rv = 0.f;
            if (mode != MODE_NONE) rv = rowv[(size_t)z * rvz + row0 + i];
            float4 v0, v1;
            if (mode == MODE_EXP) {
                v0.x = expf(acc[i][0] - rv) * scale; v0.y = expf(acc[i][1] - rv) * scale;
                v0.z = expf(acc[i][2] - rv) * scale; v0.w = expf(acc[i][3] - rv) * scale;
                v1.x = expf(acc[i][4] - rv) * scale; v1.y = expf(acc[i][5] - rv) * scale;
                v1.z = expf(acc[i][6] - rv) * scale; v1.w = expf(acc[i][7] - rv) * scale;
            } else if (mode == MODE_RSC) {
                v0.x = acc[i][0] * rv; v0.y = acc[i][1] * rv; v0.z = acc[i][2] * rv; v0.w = acc[i][3] * rv;
                v1.x = acc[i][4] * rv; v1.y = acc[i][5] * rv; v1.z = acc[i][6] * rv; v1.w = acc[i][7] * rv;
            } else {
                v0 = make_float4(acc[i][0], acc[i][1], acc[i][2], acc[i][3]);
                v1 = make_float4(acc[i][4], acc[i][5], acc[i][6], acc[i][7]);
            }
            size_t rb = (size_t)(row0 + i) * ldc;
            *reinterpret_cast<float4*>(&Cb[rb + c0]) = v0;
            *reinterpret_cast<float4*>(&Cb[rb + c1]) = v1;
        }
    } else {
        // scattered monarch-permutation store: colMem = col*cs + z*czCo
#pragma unroll
        for (int i = 0; i < 8; i++) {
            size_t rb = (size_t)(row0 + i) * ldc;
#pragma unroll
            for (int j = 0; j < 4; j++) {
                int cm = (c0 + j) * cs + z * czCo;
                float v = acc[i][j];
                if (bias) v += bias[cm];
                Cb[rb + cm] = v;
            }
#pragma unroll
            for (int j = 0; j < 4; j++) {
                int cm = (c1 + j) * cs + z * czCo;
                float v = acc[i][4 + j];
                if (bias) v += bias[cm];
                Cb[rb + cm] = v;
            }
        }
    }
}

// ---------------- TN SGEMM for kptv (split-K=4): part[z][n,m] = sum_t v[t,n]*kp[t,m]
// z = b*4 + split ; each split covers 1024 tokens. Tile 256(n) x 64(m) x 16(t).
__global__ __launch_bounds__(256, 2)
void gemm_tn_kptv(const float* __restrict__ Vg,   // kqv + 1536
                  const float* __restrict__ KPg,  // kp
                  float* __restrict__ part)
{
    const int z = blockIdx.z;
    const int b = z >> 2, s = z & 3;
    const float* Ab = Vg  + ((size_t)b * T + (size_t)s * 1024) * KQV_OUT;
    const float* Bb = KPg + ((size_t)b * T + (size_t)s * 1024) * MFEAT;
    float*       Cb = part + (size_t)z * EMB * MFEAT;

    const int nBase = blockIdx.y * TM;    // n in [0,768)
    const int mBase = blockIdx.x * TN;    // m in [0,384)

    __shared__ __align__(16) float As[TK][TM + 4];
    __shared__ __align__(16) float Bs[TK][TN + 4];

    const int tid = threadIdx.x;
    const int tx = tid & 7;
    const int ty = tid >> 3;

    // A staging: 16 t-rows x 256 n (1024 f4) -> per thread 4, contiguous f4 stores
    // B staging: 16 t-rows x 64 m (256 f4) -> per thread 1
    const int a_tk0 = tid >> 6;          // +i*4
    const int a_n4 = tid & 63;
    const int b_tk = tid >> 4;
    const int b_m4 = tid & 15;

    float4 stA[4];
    float4 stB;

    float acc[8][8];
#pragma unroll
    for (int i = 0; i < 8; i++)
#pragma unroll
        for (int j = 0; j < 8; j++) acc[i][j] = 0.f;

    const int nK = 1024 / TK;            // 64

    // prologue
#pragma unroll
    for (int i = 0; i < 4; i++) {
        int tk = a_tk0 + i * 4;
        stA[i] = *reinterpret_cast<const float4*>(&Ab[(size_t)tk * KQV_OUT + nBase + a_n4 * 4]);
    }
    stB = *reinterpret_cast<const float4*>(&Bb[(size_t)b_tk * MFEAT + mBase + b_m4 * 4]);

    int k0 = 0;
    for (int kb = 0; kb < nK; ++kb) {
#pragma unroll
        for (int i = 0; i < 4; i++) {
            int tk = a_tk0 + i * 4;
            *reinterpret_cast<float4*>(&As[tk][a_n4 * 4]) = stA[i];
        }
        *reinterpret_cast<float4*>(&Bs[b_tk][b_m4 * 4]) = stB;
        __syncthreads();

        if (kb + 1 < nK) {
            k0 += TK;
#pragma unroll
            for (int i = 0; i < 4; i++) {
                int tk = k0 + a_tk0 + i * 4;
                stA[i] = *reinterpret_cast<const float4*>(&Ab[(size_t)tk * KQV_OUT + nBase + a_n4 * 4]);
            }
            stB = *reinterpret_cast<const float4*>(&Bb[(size_t)(k0 + b_tk) * MFEAT + mBase + b_m4 * 4]);
        }

#pragma unroll
        for (int kk = 0; kk < TK; ++kk) {
            float4 a0 = *reinterpret_cast<const float4*>(&As[kk][ty * 8]);
            float4 a1 = *reinterpret_cast<const float4*>(&As[kk][ty * 8 + 4]);
            float4 b0 = *reinterpret_cast<const float4*>(&Bs[kk][tx * 4]);
            float4 b1 = *reinterpret_cast<const float4*>(&Bs[kk][tx * 4 + 32]);
            float a[8] = {a0.x, a0.y, a0.z, a0.w, a1.x, a1.y, a1.z, a1.w};
            float b[8] = {b0.x, b0.y, b0.z, b0.w, b1.x, b1.y, b1.z, b1.w};
#pragma unroll
            for (int i = 0; i < 8; i++)
#pragma unroll
                for (int j = 0; j < 8; j++)
                    acc[i][j] = fmaf(a[i], b[j], acc[i][j]);
        }
        __syncthreads();
    }

    const int row0 = nBase + ty * 8;
    const int c0 = mBase + tx * 4;
#pragma unroll
    for (int i = 0; i < 8; i++) {
        size_t rb = (size_t)(row0 + i) * MFEAT;
        *reinterpret_cast<float4*>(&Cb[rb + c0]) =
            make_float4(acc[i][0], acc[i][1], acc[i][2], acc[i][3]);
        *reinterpret_cast<float4*>(&Cb[rb + c0 + 32]) =
            make_float4(acc[i][4], acc[i][5], acc[i][6], acc[i][7]);
    }
}

__global__ void kptv_reduce(const float* __restrict__ part, float* __restrict__ kptv)
{
    size_t i = (size_t)blockIdx.x * blockDim.x + threadIdx.x;
    const size_t N = (size_t)BATCH * EMB * MFEAT;
    if (i >= N) return;
    int b = (int)(i / (EMB * MFEAT));
    size_t off = i - (size_t)b * EMB * MFEAT;
    const float* p = part + (size_t)b * 4 * EMB * MFEAT + off;
    float s = p[0] + p[(size_t)EMB * MFEAT] + p[(size_t)2 * EMB * MFEAT] + p[(size_t)3 * EMB * MFEAT];
    kptv[i] = s;
}

// ---------------- helper kernels ----------------
__global__ void xd_kernel(const float* __restrict__ kqv, float* __restrict__ xd)
{
    int warp = (blockIdx.x * blockDim.x + threadIdx.x) >> 5;
    int lane = threadIdx.x & 31;
    int bt = warp >> 1;
    int which = warp & 1;
    if (bt >= BT) return;
    const float* v = kqv + (size_t)bt * KQV_OUT + which * 768;
    float s = 0.f;
#pragma unroll 6
    for (int e = lane; e < 768; e += 32) { float x = v[e]; s = fmaf(x, x, s); }
#pragma unroll
    for (int o = 16; o; o >>= 1) s += __shfl_xor_sync(0xffffffffu, s, o);
    if (lane == 0) xd[(size_t)which * BT + bt] = 0.5f * s;
}

__global__ void ksum_partial(const float* __restrict__ kp, float* __restrict__ kpart)
{
    int b = blockIdx.x >> 5;
    int chunk = blockIdx.x & 31;
    int m = threadIdx.x;
    const float* base = kp + ((size_t)b * T + (size_t)chunk * 128) * MFEAT + m;
    float s = 0.f;
#pragma unroll 8
    for (int t = 0; t < 128; t++) s += base[(size_t)t * MFEAT];
    kpart[((size_t)b * 32 + chunk) * MFEAT + m] = s;
}

__global__ void ksum_reduce(const float* __restrict__ kpart, float* __restrict__ ksum)
{
    int idx = blockIdx.x * blockDim.x + threadIdx.x;
    if (idx >= BATCH * MFEAT) return;
    int b = idx / MFEAT, m = idx % MFEAT;
    float s = 0.f;
#pragma unroll
    for (int c = 0; c < 32; c++) s += kpart[((size_t)b * 32 + c) * MFEAT + m];
    ksum[idx] = s;
}

__global__ void dinv_kernel(const float* __restrict__ qp,
                            const float* __restrict__ ksum,
                            float* __restrict__ dinv)
{
    int warp = (blockIdx.x * blockDim.x + threadIdx.x) >> 5;
    int lane = threadIdx.x & 31;
    if (warp >= BT) return;
    int b = warp >> 12;
    const float* q  = qp + (size_t)warp * MFEAT;
    const float* ks = ksum + (size_t)b * MFEAT;
    float s = 0.f;
#pragma unroll 3
    for (int m = lane; m < MFEAT; m += 32) s = fmaf(q[m], ks[m], s);
#pragma unroll
    for (int o = 16; o; o >>= 1) s += __shfl_xor_sync(0xffffffffu, s, o);
    if (lane == 0) dinv[warp] = 1.0f / (s + EPS);
}

// ---------------- launch ----------------
extern "C" void kernel_launch(void* const* d_in, const int* in_sizes, int n_in,
                              void* d_out, int out_size)
{
    const float* x       = (const float*)d_in[0];
    const float* kqv_w1  = (const float*)d_in[1];
    const float* kqv_w2  = (const float*)d_in[2];
    const float* kqv_b   = (const float*)d_in[3];
    const float* proj_w1 = (const float*)d_in[4];
    const float* proj_w2 = (const float*)d_in[5];
    const float* proj_b  = (const float*)d_in[6];
    const float* w       = (const float*)d_in[7];
    float* out = (float*)d_out;

    float *o1, *kqv, *kpq, *xd, *kpart, *ksum, *kptvp, *kptv, *dinv, *y;
    cudaGetSymbolAddress((void**)&o1,   g_o1);
    cudaGetSymbolAddress((void**)&kqv,  g_kqv);
    cudaGetSymbolAddress((void**)&kpq,  g_kpq);
    cudaGetSymbolAddress((void**)&xd,   g_xd);
    cudaGetSymbolAddress((void**)&kpart,g_kpart);
    cudaGetSymbolAddress((void**)&ksum, g_ksum);
    cudaGetSymbolAddress((void**)&kptvp,g_kptvp);
    cudaGetSymbolAddress((void**)&kptv, g_kptv);
    cudaGetSymbolAddress((void**)&dinv, g_dinv);
    cudaGetSymbolAddress((void**)&y,    g_y);

    float* kp = kpq;
    float* qp = kpq + (size_t)BT * MFEAT;

    // 1) kqv monarch stage 1: o1p[bt, q*4+kb]
    gemm_nt<<<dim3(192/TN, BT/TM, 4), 256>>>(
        x, DIM, 192, kqv_w1, 192*192, 192,
        o1, 768, 4, 1, 0,
        nullptr, nullptr, 0, MODE_NONE, 1.f);

    // 2) kqv monarch stage 2: kqv[bt, s*4+lb] (+bias)
    gemm_nt<<<dim3(576/TN, BT/TM, 4), 256>>>(
        o1, 768, 192, kqv_w2, 576*192, 192,
        kqv, KQV_OUT, 4, 1, 0,
        kqv_b, nullptr, 0, MODE_NONE, 1.f);

    // 3) 0.5*||k||^2, 0.5*||q||^2
    xd_kernel<<<(BT*2)/8, 256>>>(kqv, xd);

    // 4) kp/qp merged: z=0 -> k, z=1 -> q
    gemm_nt<<<dim3(MFEAT/TN, BT/TM, 2), 256>>>(
        kqv, KQV_OUT, 768, w, 0, 768,
        kpq, MFEAT, 1, 0, (long long)BT * MFEAT,
        nullptr, xd, BT, MODE_EXP, PRM_SCALE);

    // 5) ksum
    ksum_partial<<<BATCH*32, MFEAT>>>(kp, kpart);
    ksum_reduce<<<(BATCH*MFEAT + 255)/256, 256>>>(kpart, ksum);

    // 6) kptv with split-K=4
    gemm_tn_kptv<<<dim3(MFEAT/TN, EMB/TM, BATCH*4), 256>>>(kqv + 1536, kp, kptvp);
    kptv_reduce<<<(BATCH*EMB*MFEAT + 255)/256, 256>>>(kptvp, kptv);

    // 7) dinv
    dinv_kernel<<<BT/8, 256>>>(qp, ksum, dinv);

    // 8) y = (qp @ kptv^T) * dinv
    gemm_nt<<<dim3(EMB/TN, T/TM, BATCH), 256>>>(
        qp, MFEAT, (long long)T * MFEAT,
        kptv, (long long)EMB * MFEAT, MFEAT,
        y, EMB, 1, 0, (long long)T * EMB,
        nullptr, dinv, T, MODE_RSC, 1.f);

    // 9) proj monarch stage 1
    gemm_nt<<<dim3(192/TN, BT/TM, 4), 256>>>(
        y, 768, 192, proj_w1, 192*192, 192,
        o1, 768, 4, 1, 0,
        nullptr, nullptr, 0, MODE_NONE, 1.f);

    // 10) proj monarch stage 2 -> output
    gemm_nt<<<dim3(192/TN, BT/TM, 4), 256>>>(
        o1, 768, 192, proj_w2, 192*192, 192,
        out, 768, 4, 1, 0,
        proj_b, nullptr, 0, MODE_NONE, 1.f);
}